// round 3
// baseline (speedup 1.0000x reference)
#include <cuda_runtime.h>
#include <math.h>

#define B_  2
#define T_  2048
#define DM  1024
#define H_  16
#define DH  64
#define BT  (B_ * T_)   // 4096

// ---------------- scratch (static device globals; no runtime alloc) ----------
__device__ float g_Q[(long long)BT * DM];     // 16.8 MB
__device__ float g_K[(long long)BT * DM];     // 16.8 MB
__device__ float g_Vs[(long long)BT * DH];    // 1 MB
__device__ float g_m[B_ * H_ * T_];
__device__ float g_l[B_ * H_ * T_];
__device__ float g_o1[(long long)BT * DH];    // 1 MB

// ---------------- generic tiled SGEMM: C = A[MxK] * B[KxN] ------------------
// 128x128 block tile, 8-deep K tile, 256 threads, 8x8 per thread (2x2 of 4x4).
__global__ __launch_bounds__(256) void sgemm128(
    const float* __restrict__ A, const float* __restrict__ Bm,
    float* __restrict__ C, int M, int N, int K,
    long long sA, long long sB, long long sC)
{
    A  += (long long)blockIdx.z * sA;
    Bm += (long long)blockIdx.z * sB;
    C  += (long long)blockIdx.z * sC;

    __shared__ float As[8][132];
    __shared__ float Bs[8][132];

    const int t  = threadIdx.x;
    const int tx = t % 16;        // 16 col groups
    const int ty = t / 16;        // 16 row groups
    const int m0 = blockIdx.y * 128;
    const int n0 = blockIdx.x * 128;

    float acc[8][8];
#pragma unroll
    for (int i = 0; i < 8; i++)
#pragma unroll
        for (int j = 0; j < 8; j++) acc[i][j] = 0.f;

    for (int k0 = 0; k0 < K; k0 += 8) {
        // A tile: 128 rows x 8 k  -> As[k][m]
#pragma unroll
        for (int p = 0; p < 4; p++) {
            int idx = t + 256 * p;          // 0..1023
            int m = idx >> 3, k = idx & 7;
            int gm = m0 + m;
            As[k][m] = (gm < M) ? A[(long long)gm * K + (k0 + k)] : 0.f;
        }
        // B tile: 8 k x 128 cols -> Bs[k][n]
#pragma unroll
        for (int p = 0; p < 4; p++) {
            int idx = t + 256 * p;
            int k = idx >> 7, n = idx & 127;
            int gn = n0 + n;
            Bs[k][n] = (gn < N) ? Bm[(long long)(k0 + k) * N + gn] : 0.f;
        }
        __syncthreads();

#pragma unroll
        for (int kk = 0; kk < 8; kk++) {
            float a[8], b[8];
#pragma unroll
            for (int i = 0; i < 4; i++) {
                a[i]     = As[kk][ty * 4 + i];
                a[4 + i] = As[kk][64 + ty * 4 + i];
            }
#pragma unroll
            for (int j = 0; j < 4; j++) {
                b[j]     = Bs[kk][tx * 4 + j];
                b[4 + j] = Bs[kk][64 + tx * 4 + j];
            }
#pragma unroll
            for (int i = 0; i < 8; i++)
#pragma unroll
                for (int j = 0; j < 8; j++)
                    acc[i][j] += a[i] * b[j];
        }
        __syncthreads();
    }

#pragma unroll
    for (int i = 0; i < 8; i++) {
        int gm = m0 + ((i < 4) ? (ty * 4 + i) : (64 + ty * 4 + (i - 4)));
        if (gm >= M) continue;
#pragma unroll
        for (int j = 0; j < 8; j++) {
            int gn = n0 + ((j < 4) ? (tx * 4 + j) : (64 + tx * 4 + (j - 4)));
            if (gn < N) C[(long long)gm * N + gn] = acc[i][j];
        }
    }
}

// ---------------- pass A: per-(b,h,row) online softmax stats ----------------
// grid: (T/32, H, B), 256 threads. Each block: 32 query rows, one head.
__global__ __launch_bounds__(256) void pass_a()
{
    const int i0 = blockIdx.x * 32;
    const int h  = blockIdx.y;
    const int b  = blockIdx.z;
    const int t  = threadIdx.x;
    const int r  = t >> 3;          // row within block (0..31)
    const int c  = t & 7;           // 8 threads per row
    const int i  = i0 + r;

    __shared__ float Qs[32][68];
    __shared__ float Ks[64][68];

    const float* Qbase = g_Q + ((long long)(b * T_ + i0)) * DM + h * DH;
    const float* Kbase = g_K + ((long long)(b * T_)) * DM + h * DH;

    for (int p = t; p < 32 * 64; p += 256) {
        int rr = p >> 6, d = p & 63;
        Qs[rr][d] = Qbase[(long long)rr * DM + d];
    }

    float m_run = -INFINITY, l_run = 0.f;
    const int jmax = i0 + 31;

    for (int jt = 0; jt <= jmax; jt += 64) {
        __syncthreads();
        for (int p = t; p < 64 * 64; p += 256) {
            int rr = p >> 6, d = p & 63;
            int j = jt + rr;
            Ks[rr][d] = (j < T_) ? Kbase[(long long)j * DM + d] : 0.f;
        }
        __syncthreads();

        float s[8];
#pragma unroll
        for (int u = 0; u < 8; u++) s[u] = 0.f;
#pragma unroll
        for (int d = 0; d < 64; d += 4) {
            float4 qv = *reinterpret_cast<const float4*>(&Qs[r][d]);
#pragma unroll
            for (int u = 0; u < 8; u++) {
                float4 kv = *reinterpret_cast<const float4*>(&Ks[c + 8 * u][d]);
                s[u] += qv.x * kv.x + qv.y * kv.y + qv.z * kv.z + qv.w * kv.w;
            }
        }

        float tmax = -INFINITY;
#pragma unroll
        for (int u = 0; u < 8; u++) {
            int j = jt + c + 8 * u;
            s[u] = (j <= i) ? s[u] * 0.125f : -INFINITY;
            tmax = fmaxf(tmax, s[u]);
        }
#pragma unroll
        for (int o = 1; o < 8; o <<= 1)
            tmax = fmaxf(tmax, __shfl_xor_sync(0xffffffffu, tmax, o));

        float nm = fmaxf(m_run, tmax);
        if (nm > -INFINITY) {
            float ps = 0.f;
#pragma unroll
            for (int u = 0; u < 8; u++)
                if (s[u] > -INFINITY) ps += __expf(s[u] - nm);
#pragma unroll
            for (int o = 1; o < 8; o <<= 1)
                ps += __shfl_xor_sync(0xffffffffu, ps, o);
            l_run = l_run * __expf(m_run - nm) + ps;
            m_run = nm;
        }
    }

    if (c == 0) {
        g_m[(b * H_ + h) * T_ + i] = m_run;
        g_l[(b * H_ + h) * T_ + i] = l_run;
    }
}

// ---------------- pass B: head-averaged attention matrix --------------------
// grid: (T/64, T/32, B). Block: 32 query rows x 64 key cols, loop 16 heads.
__global__ __launch_bounds__(256) void pass_b(float* __restrict__ attn)
{
    const int j0 = blockIdx.x * 64;
    const int i0 = blockIdx.y * 32;
    const int b  = blockIdx.z;
    const int t  = threadIdx.x;
    const int r  = t >> 3;
    const int c  = t & 7;
    const int i  = i0 + r;

    float* orow = attn + ((long long)(b * T_ + i)) * T_;

    if (j0 > i0 + 31) {   // tile entirely above the diagonal: zeros only
#pragma unroll
        for (int u = 0; u < 8; u++) orow[j0 + c + 8 * u] = 0.f;
        return;
    }

    __shared__ float Qs[32][68];
    __shared__ float Ks[64][68];

    float a_acc[8];
#pragma unroll
    for (int u = 0; u < 8; u++) a_acc[u] = 0.f;

    for (int h = 0; h < H_; h++) {
        __syncthreads();
        const float* Qbase = g_Q + ((long long)(b * T_ + i0)) * DM + h * DH;
        const float* Kbase = g_K + ((long long)(b * T_ + j0)) * DM + h * DH;
        for (int p = t; p < 32 * 64; p += 256) {
            int rr = p >> 6, d = p & 63;
            Qs[rr][d] = Qbase[(long long)rr * DM + d];
        }
        for (int p = t; p < 64 * 64; p += 256) {
            int rr = p >> 6, d = p & 63;
            int j = j0 + rr;
            Ks[rr][d] = (j < T_) ? Kbase[(long long)rr * DM + d] : 0.f;
        }
        __syncthreads();

        float s[8];
#pragma unroll
        for (int u = 0; u < 8; u++) s[u] = 0.f;
#pragma unroll
        for (int d = 0; d < 64; d += 4) {
            float4 qv = *reinterpret_cast<const float4*>(&Qs[r][d]);
#pragma unroll
            for (int u = 0; u < 8; u++) {
                float4 kv = *reinterpret_cast<const float4*>(&Ks[c + 8 * u][d]);
                s[u] += qv.x * kv.x + qv.y * kv.y + qv.z * kv.z + qv.w * kv.w;
            }
        }

        const float mh   = g_m[(b * H_ + h) * T_ + i];
        const float coef = 1.f / (16.f * g_l[(b * H_ + h) * T_ + i]);
#pragma unroll
        for (int u = 0; u < 8; u++) {
            int j = j0 + c + 8 * u;
            if (j <= i) a_acc[u] += __expf(s[u] * 0.125f - mh) * coef;
        }
    }

#pragma unroll
    for (int u = 0; u < 8; u++) {
        int j = j0 + c + 8 * u;
        orow[j] = (j <= i) ? a_acc[u] : 0.f;
    }
}

// ---------------- launch ----------------------------------------------------
extern "C" void kernel_launch(void* const* d_in, const int* in_sizes, int n_in,
                              void* d_out, int out_size)
{
    const float* q  = (const float*)d_in[0];
    const float* k  = (const float*)d_in[1];
    const float* v  = (const float*)d_in[2];
    // d_in[3] = mask (tril) — causality applied analytically
    const float* Wq = (const float*)d_in[4];
    const float* Wk = (const float*)d_in[5];
    const float* Wv = (const float*)d_in[6];
    const float* Wo = (const float*)d_in[7];

    float* out  = (float*)d_out;
    float* attn = out + (long long)BT * DM;   // second tuple element

    float *Qp, *Kp, *Vp, *O1p;
    cudaGetSymbolAddress((void**)&Qp,  g_Q);
    cudaGetSymbolAddress((void**)&Kp,  g_K);
    cudaGetSymbolAddress((void**)&Vp,  g_Vs);
    cudaGetSymbolAddress((void**)&O1p, g_o1);

    // 1-3: projections
    sgemm128<<<dim3(DM / 128, BT / 128, 1), 256>>>(q, Wq, Qp, BT, DM, DM, 0, 0, 0);
    sgemm128<<<dim3(DM / 128, BT / 128, 1), 256>>>(k, Wk, Kp, BT, DM, DM, 0, 0, 0);
    sgemm128<<<dim3(1,        BT / 128, 1), 256>>>(v, Wv, Vp, BT, DH, DM, 0, 0, 0);

    // 4: softmax stats per (b, h, row)
    pass_a<<<dim3(T_ / 32, H_, B_), 256>>>();

    // 5: head-averaged attention matrix (second output)
    pass_b<<<dim3(T_ / 64, T_ / 32, B_), 256>>>(attn);

    // 6: out1 = attn_avg @ V_shared   (per batch)
    sgemm128<<<dim3(1, T_ / 128, B_), 256>>>(attn, Vp, O1p, T_, DH, T_,
                                             (long long)T_ * T_,
                                             (long long)T_ * DH,
                                             (long long)T_ * DH);

    // 7: out = out1 @ Wo
    sgemm128<<<dim3(DM / 128, BT / 128, 1), 256>>>(O1p, Wo, out, BT, DM, DH, 0, 0, 0);
}

// round 5
// speedup vs baseline: 1.3842x; 1.3842x over previous
#include <cuda_runtime.h>
#include <math.h>

#define B_  2
#define T_  2048
#define DM  1024
#define H_  16
#define DH  64
#define BT  (B_ * T_)   // 4096

// ---------------- scratch (static device globals; no runtime alloc) ----------
__device__ float g_Q[(long long)BT * DM];     // 16.8 MB
__device__ float g_K[(long long)BT * DM];     // 16.8 MB
__device__ float g_Vs[(long long)BT * DH];    // 1 MB
__device__ float g_m[B_ * H_ * T_];
__device__ float g_l[B_ * H_ * T_];
__device__ float g_o1[(long long)BT * DH];    // 1 MB

// ---------------- generic tiled SGEMM: C = A[MxK] * B[KxN] ------------------
__global__ __launch_bounds__(256) void sgemm128(
    const float* __restrict__ A, const float* __restrict__ Bm,
    float* __restrict__ C, int M, int N, int K,
    long long sA, long long sB, long long sC)
{
    A  += (long long)blockIdx.z * sA;
    Bm += (long long)blockIdx.z * sB;
    C  += (long long)blockIdx.z * sC;

    __shared__ float As[8][132];
    __shared__ float Bs[8][132];

    const int t  = threadIdx.x;
    const int tx = t % 16;
    const int ty = t / 16;
    const int m0 = blockIdx.y * 128;
    const int n0 = blockIdx.x * 128;

    float acc[8][8];
#pragma unroll
    for (int i = 0; i < 8; i++)
#pragma unroll
        for (int j = 0; j < 8; j++) acc[i][j] = 0.f;

    for (int k0 = 0; k0 < K; k0 += 8) {
#pragma unroll
        for (int p = 0; p < 4; p++) {
            int idx = t + 256 * p;
            int m = idx >> 3, k = idx & 7;
            int gm = m0 + m;
            As[k][m] = (gm < M) ? A[(long long)gm * K + (k0 + k)] : 0.f;
        }
#pragma unroll
        for (int p = 0; p < 4; p++) {
            int idx = t + 256 * p;
            int k = idx >> 7, n = idx & 127;
            int gn = n0 + n;
            Bs[k][n] = (gn < N) ? Bm[(long long)(k0 + k) * N + gn] : 0.f;
        }
        __syncthreads();

#pragma unroll
        for (int kk = 0; kk < 8; kk++) {
            float a[8], b[8];
#pragma unroll
            for (int i = 0; i < 4; i++) {
                a[i]     = As[kk][ty * 4 + i];
                a[4 + i] = As[kk][64 + ty * 4 + i];
            }
#pragma unroll
            for (int j = 0; j < 4; j++) {
                b[j]     = Bs[kk][tx * 4 + j];
                b[4 + j] = Bs[kk][64 + tx * 4 + j];
            }
#pragma unroll
            for (int i = 0; i < 8; i++)
#pragma unroll
                for (int j = 0; j < 8; j++)
                    acc[i][j] += a[i] * b[j];
        }
        __syncthreads();
    }

#pragma unroll
    for (int i = 0; i < 8; i++) {
        int gm = m0 + ((i < 4) ? (ty * 4 + i) : (64 + ty * 4 + (i - 4)));
        if (gm >= M) continue;
#pragma unroll
        for (int j = 0; j < 8; j++) {
            int gn = n0 + ((j < 4) ? (tx * 4 + j) : (64 + tx * 4 + (j - 4)));
            if (gn < N) C[(long long)gm * N + gn] = acc[i][j];
        }
    }
}

// ---------------- pass A: per-(b,h,row) online softmax stats ----------------
// 128q x 128k tiles, 8q x 8k per thread (strided). Dynamic smem: Qs|Ks.
#define PA_LD 68
__global__ __launch_bounds__(256) void pass_a()
{
    extern __shared__ float sm[];
    float* Qs = sm;                    // [128][68]
    float* Ks = sm + 128 * PA_LD;      // [128][68]

    const int i0 = blockIdx.x * 128;
    const int h  = blockIdx.y;
    const int b  = blockIdx.z;
    const int t  = threadIdx.x;
    const int tx = t & 15;             // k group
    const int ty = t >> 4;             // q group

    const float* Qbase = g_Q + ((long long)(b * T_ + i0)) * DM + h * DH;
    const float* Kbase = g_K + ((long long)(b * T_)) * DM + h * DH;

    // Q tile: 128 rows x 64 cols (16 float4 per row)
#pragma unroll
    for (int p = 0; p < 8; p++) {
        int idx = t + 256 * p;
        int rr = idx >> 4, dq = (idx & 15) * 4;
        *(float4*)&Qs[rr * PA_LD + dq] =
            *(const float4*)&Qbase[(long long)rr * DM + dq];
    }

    float m_run[8], l_run[8];
#pragma unroll
    for (int v = 0; v < 8; v++) { m_run[v] = -INFINITY; l_run[v] = 0.f; }

    for (int jt = 0; jt <= i0; jt += 128) {
        __syncthreads();
#pragma unroll
        for (int p = 0; p < 8; p++) {
            int idx = t + 256 * p;
            int rr = idx >> 4, dq = (idx & 15) * 4;
            *(float4*)&Ks[rr * PA_LD + dq] =
                *(const float4*)&Kbase[(long long)(jt + rr) * DM + dq];
        }
        __syncthreads();

        float s[8][8];
#pragma unroll
        for (int v = 0; v < 8; v++)
#pragma unroll
            for (int u = 0; u < 8; u++) s[v][u] = 0.f;

        const float* kp = &Ks[tx * PA_LD];
        const float* qp = &Qs[ty * PA_LD];
#pragma unroll 2
        for (int d = 0; d < 64; d += 4) {
            float4 kv[8];
#pragma unroll
            for (int u = 0; u < 8; u++)
                kv[u] = *(const float4*)&kp[u * 16 * PA_LD + d];
#pragma unroll
            for (int v = 0; v < 8; v++) {
                float4 qv = *(const float4*)&qp[v * 16 * PA_LD + d];
#pragma unroll
                for (int u = 0; u < 8; u++) {
                    s[v][u] += qv.x * kv[u].x;
                    s[v][u] += qv.y * kv[u].y;
                    s[v][u] += qv.z * kv[u].z;
                    s[v][u] += qv.w * kv[u].w;
                }
            }
        }

        const bool diag = (jt == i0);
#pragma unroll
        for (int v = 0; v < 8; v++) {
            const int i = i0 + ty + 16 * v;
            float tmax = -INFINITY;
#pragma unroll
            for (int u = 0; u < 8; u++) {
                float sv = s[v][u] * 0.125f;
                if (diag && (jt + tx + 16 * u) > i) sv = -INFINITY;
                s[v][u] = sv;
                tmax = fmaxf(tmax, sv);
            }
#pragma unroll
            for (int o = 1; o < 16; o <<= 1)
                tmax = fmaxf(tmax, __shfl_xor_sync(0xffffffffu, tmax, o));

            float nm = fmaxf(m_run[v], tmax);
            float ps = 0.f;
#pragma unroll
            for (int u = 0; u < 8; u++) ps += __expf(s[v][u] - nm);
#pragma unroll
            for (int o = 1; o < 16; o <<= 1)
                ps += __shfl_xor_sync(0xffffffffu, ps, o);
            l_run[v] = l_run[v] * __expf(m_run[v] - nm) + ps;
            m_run[v] = nm;
        }
    }

    if (tx == 0) {
#pragma unroll
        for (int v = 0; v < 8; v++) {
            int i = i0 + ty + 16 * v;
            g_m[(b * H_ + h) * T_ + i] = m_run[v];
            g_l[(b * H_ + h) * T_ + i] = l_run[v];
        }
    }
}

// ---------------- pass B: head-averaged attention matrix --------------------
// 128q x 64k tiles, 8q x 4k per thread, loop 16 heads. Dynamic smem.
__global__ __launch_bounds__(256) void pass_b(float* __restrict__ attn)
{
    extern __shared__ float sm[];
    float* Qs = sm;                          // [128][68]
    float* Ks = sm + 128 * PA_LD;            // [64][68]
    float* ms = sm + 192 * PA_LD;            // [16][128]
    float* cs = ms + 16 * 128;               // [16][128]

    const int j0 = blockIdx.x * 64;
    const int i0 = blockIdx.y * 128;
    const int b  = blockIdx.z;
    const int t  = threadIdx.x;
    const int tx = t & 15;                   // k group
    const int ty = t >> 4;                   // q group

    if (j0 > i0 + 127) {                     // fully above diagonal: zeros
#pragma unroll
        for (int p = 0; p < 8; p++) {
            int idx = t + 256 * p;
            int rr = idx >> 4, c = (idx & 15) * 4;
            float4 z = make_float4(0.f, 0.f, 0.f, 0.f);
            *(float4*)&attn[((long long)(b * T_ + i0 + rr)) * T_ + j0 + c] = z;
        }
        return;
    }

    // preload softmax stats for this i-block, all heads
    for (int p = t; p < H_ * 128; p += 256) {
        int hh = p >> 7, rr = p & 127;
        ms[p] = g_m[(b * H_ + hh) * T_ + i0 + rr];
        cs[p] = 1.f / (16.f * g_l[(b * H_ + hh) * T_ + i0 + rr]);
    }

    const bool need_mask = (j0 + 63 > i0);

    float a[8][4];
#pragma unroll
    for (int v = 0; v < 8; v++)
#pragma unroll
        for (int u = 0; u < 4; u++) a[v][u] = 0.f;

    for (int h = 0; h < H_; h++) {
        __syncthreads();
        const float* Qbase = g_Q + ((long long)(b * T_ + i0)) * DM + h * DH;
        const float* Kbase = g_K + ((long long)(b * T_ + j0)) * DM + h * DH;
#pragma unroll
        for (int p = 0; p < 8; p++) {
            int idx = t + 256 * p;
            int rr = idx >> 4, dq = (idx & 15) * 4;
            *(float4*)&Qs[rr * PA_LD + dq] =
                *(const float4*)&Qbase[(long long)rr * DM + dq];
        }
#pragma unroll
        for (int p = 0; p < 4; p++) {
            int idx = t + 256 * p;
            int rr = idx >> 4, dq = (idx & 15) * 4;
            *(float4*)&Ks[rr * PA_LD + dq] =
                *(const float4*)&Kbase[(long long)rr * DM + dq];
        }
        __syncthreads();

        float s[8][4];
#pragma unroll
        for (int v = 0; v < 8; v++)
#pragma unroll
            for (int u = 0; u < 4; u++) s[v][u] = 0.f;

        const float* kp = &Ks[tx * PA_LD];
        const float* qp = &Qs[ty * PA_LD];
#pragma unroll 2
        for (int d = 0; d < 64; d += 4) {
            float4 kv[4];
#pragma unroll
            for (int u = 0; u < 4; u++)
                kv[u] = *(const float4*)&kp[u * 16 * PA_LD + d];
#pragma unroll
            for (int v = 0; v < 8; v++) {
                float4 qv = *(const float4*)&qp[v * 16 * PA_LD + d];
#pragma unroll
                for (int u = 0; u < 4; u++) {
                    s[v][u] += qv.x * kv[u].x;
                    s[v][u] += qv.y * kv[u].y;
                    s[v][u] += qv.z * kv[u].z;
                    s[v][u] += qv.w * kv[u].w;
                }
            }
        }

#pragma unroll
        for (int v = 0; v < 8; v++) {
            const int i  = i0 + ty + 16 * v;
            const float mh   = ms[h * 128 + ty + 16 * v];
            const float coef = cs[h * 128 + ty + 16 * v];
            if (need_mask) {
#pragma unroll
                for (int u = 0; u < 4; u++) {
                    int j = j0 + tx + 16 * u;
                    if (j <= i)
                        a[v][u] += __expf(s[v][u] * 0.125f - mh) * coef;
                }
            } else {
#pragma unroll
                for (int u = 0; u < 4; u++)
                    a[v][u] += __expf(s[v][u] * 0.125f - mh) * coef;
            }
        }
    }

#pragma unroll
    for (int v = 0; v < 8; v++) {
        const int i = i0 + ty + 16 * v;
        float* orow = attn + ((long long)(b * T_ + i)) * T_;
#pragma unroll
        for (int u = 0; u < 4; u++)
            orow[j0 + tx + 16 * u] = a[v][u];
    }
}

// ---------------- launch ----------------------------------------------------
extern "C" void kernel_launch(void* const* d_in, const int* in_sizes, int n_in,
                              void* d_out, int out_size)
{
    const float* q  = (const float*)d_in[0];
    const float* k  = (const float*)d_in[1];
    const float* v  = (const float*)d_in[2];
    // d_in[3] = mask (tril) — causality applied analytically
    const float* Wq = (const float*)d_in[4];
    const float* Wk = (const float*)d_in[5];
    const float* Wv = (const float*)d_in[6];
    const float* Wo = (const float*)d_in[7];

    float* out  = (float*)d_out;
    float* attn = out + (long long)BT * DM;

    float *Qp, *Kp, *Vp, *O1p;
    cudaGetSymbolAddress((void**)&Qp,  g_Q);
    cudaGetSymbolAddress((void**)&Kp,  g_K);
    cudaGetSymbolAddress((void**)&Vp,  g_Vs);
    cudaGetSymbolAddress((void**)&O1p, g_o1);

    const int smem_a = 2 * 128 * PA_LD * 4;                       // 69632
    const int smem_b = (192 * PA_LD + 2 * 16 * 128) * 4;          // 68608
    static bool attr_set = false;
    if (!attr_set) {
        cudaFuncSetAttribute(pass_a, cudaFuncAttributeMaxDynamicSharedMemorySize, smem_a);
        cudaFuncSetAttribute(pass_b, cudaFuncAttributeMaxDynamicSharedMemorySize, smem_b);
        attr_set = true;
    }

    // 1-3: projections
    sgemm128<<<dim3(DM / 128, BT / 128, 1), 256>>>(q, Wq, Qp, BT, DM, DM, 0, 0, 0);
    sgemm128<<<dim3(DM / 128, BT / 128, 1), 256>>>(k, Wk, Kp, BT, DM, DM, 0, 0, 0);
    sgemm128<<<dim3(1,        BT / 128, 1), 256>>>(v, Wv, Vp, BT, DH, DM, 0, 0, 0);

    // 4: softmax stats
    pass_a<<<dim3(T_ / 128, H_, B_), 256, smem_a>>>();

    // 5: head-averaged attention matrix
    pass_b<<<dim3(T_ / 64, T_ / 128, B_), 256, smem_b>>>(attn);

    // 6: out1 = attn_avg @ V_shared
    sgemm128<<<dim3(1, T_ / 128, B_), 256>>>(attn, Vp, O1p, T_, DH, T_,
                                             (long long)T_ * T_,
                                             (long long)T_ * DH,
                                             (long long)T_ * DH);

    // 7: out = out1 @ Wo
    sgemm128<<<dim3(DM / 128, BT / 128, 1), 256>>>(O1p, Wo, out, BT, DM, DH, 0, 0, 0);
}